// round 15
// baseline (speedup 1.0000x reference)
#include <cuda_runtime.h>
#include <cuda_fp16.h>
#include <cstdint>

#define HB   4
#define CIN  256
#define HID  16
#define IMGH 192
#define IMGW 192
#define HW   (IMGH*IMGW)        // 36864
#define HBHW (HB*HW)            // 147456
#define COUT 128
#define CCAT 288

typedef unsigned int uint;

// ---------------- scratch (device globals; no allocation) ----------------
__device__ __half2 g_h2[2][(size_t)8*HBHW];      // h pairs [br][b*8+c2][HW]
__device__ __half  g_wkh[10*16*256];             // conv taps [t][o][ci]
__device__ __half  g_woh[COUT*CCAT];             // out weights [o][i]
__device__ __half  g_ubwh[2*432*18];             // branch GEMM B hi (sgn folded)
__device__ __half  g_ubwl[2*432*18];
__device__ uint4   g_u12v[(size_t)2*18*HBHW*2];  // u1,u2 [br][grp][px][32B]
__device__ float4  g_u3v[(size_t)2*9*HBHW*4];    // u3    [br][q][px][64B]

__constant__ int c_dy[9] = {-1,-1,-1, 0, 1, 1, 1, 0, 0};
__constant__ int c_dx[9] = {-1, 0, 1, 1, 1, 0,-1,-1, 0};

__device__ __forceinline__ void h2split(float v, __half& h, __half& l)
{
    h = __float2half_rn(v);
    l = __float2half_rn(v - __half2float(h));
}
__device__ __forceinline__ uint lduh(const __half* p) { return *(const uint*)p; }

__device__ __forceinline__ void mma16816(float* d,
                                         uint a0, uint a1, uint a2, uint a3,
                                         uint b0, uint b1)
{
    asm volatile("mma.sync.aligned.m16n8k16.row.col.f32.f16.f16.f32 "
        "{%0,%1,%2,%3}, {%4,%5,%6,%7}, {%8,%9}, {%0,%1,%2,%3};"
        : "+f"(d[0]), "+f"(d[1]), "+f"(d[2]), "+f"(d[3])
        : "r"(a0), "r"(a1), "r"(a2), "r"(a3), "r"(b0), "r"(b1));
}

// ---------------- prep ----------------
__global__ void k_prep(const float* __restrict__ w3c,
                       const float* __restrict__ w1c,
                       const float* __restrict__ wo,
                       const float* __restrict__ w1_0, const float* __restrict__ w2_0,
                       const float* __restrict__ w3_0,
                       const float* __restrict__ w1_1, const float* __restrict__ w2_1,
                       const float* __restrict__ w3_1)
{
    int idx = blockIdx.x*256 + threadIdx.x;
    const int N1 = 10*16*256;
    const int N2 = COUT*CCAT;
    if (idx < N1) {
        int t  = idx >> 12;
        int o  = (idx >> 8) & 15;
        int ci = idx & 255;
        float v = (t < 9) ? w3c[(o*256 + ci)*9 + t] : w1c[o*256 + ci];
        g_wkh[idx] = __float2half_rn(v);
    } else if (idx < N1 + N2) {
        int j = idx - N1;
        g_woh[j] = __float2half_rn(wo[j]);
    } else if (idx < N1 + N2 + 2*432*18) {
        int j2 = idx - N1 - N2;
        int br = j2 / (432*18);
        int rem = j2 - br*(432*18);
        int n = rem / 18;
        int k = rem - n*18;
        int jj = n / 144;
        int g  = (n >> 4) % 9;
        int d  = n & 15;
        float v = 0.f;
        if (k < 16) {
            const float* src = (br == 0)
                ? ((jj == 0) ? w1_0 : (jj == 1) ? w2_0 : w3_0)
                : ((jj == 0) ? w1_1 : (jj == 1) ? w2_1 : w3_1);
            v = src[g*256 + d*16 + k];
            if (g < 8) v = -v;
        }
        __half h, l; h2split(v, h, l);
        g_ubwh[j2] = h; g_ubwl[j2] = l;
    }
}

// ---------------- K1: fused conv via HMMA, 1-term, half2 epilogue --------
#define A_PLANE 15552
#define B_PLANE 5760
__global__ void __launch_bounds__(256)
k_conv_mma(const float* __restrict__ cen,
           const float* __restrict__ b0v,
           const float* __restrict__ b1v)
{
    extern __shared__ __half smc[];
    __half* Ah = smc;
    __half* Bh = Ah + A_PLANE;

    int tid  = threadIdx.x;
    int lane = tid & 31;
    int wid  = tid >> 5;
    int y_l  = wid & 3;
    int xh   = wid >> 2;

    int bx = blockIdx.x % 3;
    int yt = (blockIdx.x / 3) % 48;
    int bb = blockIdx.x / 144;
    int x0 = bx*64, y0 = yt*4;

    const int tdy[10] = {-1,-1,-1, 0, 0, 0, 1, 1, 1, 0};
    const int tdx[10] = {-1, 0, 1,-1, 0, 1,-1, 0, 1, 0};

    float acc1[2][2][4];
    float acc0[2][2][4];
    #pragma unroll
    for (int mt = 0; mt < 2; mt++)
        #pragma unroll
        for (int nt = 0; nt < 2; nt++)
            #pragma unroll
            for (int i = 0; i < 4; i++) { acc1[mt][nt][i] = 0.f; acc0[mt][nt][i] = 0.f; }

    int g  = lane >> 2;
    int k0 = 2*(lane & 3);
    int e0 = ((y_l + 1)*72 + (xh*32 + g + 1))*36;

    for (int ci0 = 0; ci0 < CIN; ci0 += 32) {
        __syncthreads();
        for (int j = tid; j < 32*6*68; j += 256) {
            int sx = j % 68;
            int r2 = j / 68;
            int sy = r2 % 6;
            int ci = r2 / 6;
            int gy = y0 - 1 + sy, gx = x0 - 1 + sx;
            float v = 0.f;
            if ((unsigned)gy < (unsigned)IMGH && (unsigned)gx < (unsigned)IMGW)
                v = __ldg(&cen[((size_t)(bb*CIN + ci0 + ci))*HW + gy*IMGW + gx]);
            Ah[(sy*72 + sx)*36 + ci] = __float2half_rn(v);
        }
        for (int j = tid; j < 10*16*32; j += 256) {
            int ci = j & 31;
            int o  = (j >> 5) & 15;
            int t  = j >> 9;
            Bh[(t*16 + o)*36 + ci] = g_wkh[(t*16 + o)*256 + ci0 + ci];
        }
        __syncthreads();

        #pragma unroll 1
        for (int t = 0; t < 10; t++) {
            int aoff = (tdy[t]*72 + tdx[t])*36;
            #pragma unroll
            for (int ks = 0; ks < 32; ks += 16) {
                uint bh[2][2];
                #pragma unroll
                for (int nt = 0; nt < 2; nt++) {
                    int bbase = (t*16 + nt*8 + g)*36 + ks + k0;
                    bh[nt][0] = lduh(&Bh[bbase]);     bh[nt][1] = lduh(&Bh[bbase+8]);
                }
                #pragma unroll
                for (int mt = 0; mt < 2; mt++) {
                    int ab = e0 + aoff + mt*16*36 + ks + k0;
                    uint ah0 = lduh(&Ah[ab]),         ah1 = lduh(&Ah[ab+8*36]);
                    uint ah2 = lduh(&Ah[ab+8]),       ah3 = lduh(&Ah[ab+8*36+8]);
                    float (*acc)[4] = (t < 9) ? acc1[mt] : acc0[mt];
                    #pragma unroll
                    for (int nt = 0; nt < 2; nt++)
                        mma16816(acc[nt], ah0, ah1, ah2, ah3, bh[nt][0], bh[nt][1]);
                }
            }
        }
    }

    #pragma unroll
    for (int mt = 0; mt < 2; mt++) {
        #pragma unroll
        for (int nt = 0; nt < 2; nt++) {
            int c2 = nt*4 + (lane & 3);
            float bv0 = __ldg(&b1v[2*c2]), bv1 = __ldg(&b1v[2*c2+1]);
            float av0 = __ldg(&b0v[2*c2]), av1 = __ldg(&b0v[2*c2+1]);
            int gx = x0 + xh*32 + mt*16 + (lane >> 2);
            int gy = y0 + y_l;
            size_t ofs = ((size_t)(bb*8 + c2))*HW + gy*IMGW + gx;
            g_h2[1][ofs]     = __floats2half2_rn(acc1[mt][nt][0]+bv0, acc1[mt][nt][1]+bv1);
            g_h2[1][ofs + 8] = __floats2half2_rn(acc1[mt][nt][2]+bv0, acc1[mt][nt][3]+bv1);
            g_h2[0][ofs]     = __floats2half2_rn(acc0[mt][nt][0]+av0, acc0[mt][nt][1]+av1);
            g_h2[0][ofs + 8] = __floats2half2_rn(acc0[mt][nt][2]+av0, acc0[mt][nt][3]+av1);
        }
    }
}

// ---------------- K2: u-GEMM, 2-term, vectorized epilogue ----------------
__global__ void __launch_bounds__(256)
k_ugemm(int br)
{
    extern __shared__ __half smu[];
    __half* Ah = smu;                    // 128*18
    __half* Bh = Ah + 128*18;            // 432*18
    __half* Bl = Bh + 432*18;
    float*  epi = (float*)(Bl + 432*18); // 48*130

    int tid  = threadIdx.x;
    int lane = tid & 31;
    int wid  = tid >> 5;

    int gid0 = blockIdx.x*128;
    int bb = gid0 / HW;
    int p0 = gid0 - bb*HW;

    for (int idx = tid; idx < 432*18; idx += 256) {
        Bh[idx] = g_ubwh[br*432*18 + idx];
        Bl[idx] = g_ubwl[br*432*18 + idx];
    }
    for (int idx = tid; idx < 128*8; idx += 256) {
        int c2 = idx >> 7, px = idx & 127;
        __half2 v = g_h2[br][((size_t)(bb*8 + c2))*HW + p0 + px];
        *(__half2*)&Ah[px*18 + 2*c2] = v;
    }
    __syncthreads();

    int m0 = wid*16;
    int gr = lane >> 2;
    int k0 = 2*(lane & 3);
    int ab = (m0 + gr)*18 + k0;
    uint ah0 = lduh(&Ah[ab]),      ah1 = lduh(&Ah[ab + 8*18]);
    uint ah2 = lduh(&Ah[ab+8]),    ah3 = lduh(&Ah[ab + 8*18 + 8]);

    for (int nc = 0; nc < 9; nc++) {
        float acc[6][4];
        #pragma unroll
        for (int nt = 0; nt < 6; nt++)
            #pragma unroll
            for (int i = 0; i < 4; i++) acc[nt][i] = 0.f;

        #pragma unroll
        for (int nt = 0; nt < 6; nt++) {
            int n8 = (nc*6 + nt)*8;
            int bbase = (n8 + gr)*18 + k0;
            uint bh0 = lduh(&Bh[bbase]), bh1 = lduh(&Bh[bbase+8]);
            uint bl0 = lduh(&Bl[bbase]), bl1 = lduh(&Bl[bbase+8]);
            mma16816(acc[nt], ah0, ah1, ah2, ah3, bh0, bh1);
            mma16816(acc[nt], ah0, ah1, ah2, ah3, bl0, bl1);
        }
        __syncthreads();
        #pragma unroll
        for (int nt = 0; nt < 6; nt++) {
            #pragma unroll
            for (int i = 0; i < 4; i++) {
                int col = nt*8 + 2*(lane & 3) + (i & 1);
                int row = m0 + gr + ((i >= 2) ? 8 : 0);
                epi[col*130 + row] = acc[nt][i];
            }
        }
        __syncthreads();
        if (nc < 6) {
            for (int idx = tid; idx < 3*128; idx += 256) {
                int g3 = idx >> 7, px = idx & 127;
                int gg = nc*3 + g3;                 // 0..17 (u1 then u2)
                const float* ec = epi + (g3*16)*130 + px;
                __half2 h0 = __floats2half2_rn(ec[0*130],  ec[1*130]);
                __half2 h1 = __floats2half2_rn(ec[2*130],  ec[3*130]);
                __half2 h2 = __floats2half2_rn(ec[4*130],  ec[5*130]);
                __half2 h3 = __floats2half2_rn(ec[6*130],  ec[7*130]);
                __half2 h4 = __floats2half2_rn(ec[8*130],  ec[9*130]);
                __half2 h5 = __floats2half2_rn(ec[10*130], ec[11*130]);
                __half2 h6 = __floats2half2_rn(ec[12*130], ec[13*130]);
                __half2 h7 = __floats2half2_rn(ec[14*130], ec[15*130]);
                uint4 lo = make_uint4(*(uint*)&h0, *(uint*)&h1, *(uint*)&h2, *(uint*)&h3);
                uint4 hi = make_uint4(*(uint*)&h4, *(uint*)&h5, *(uint*)&h6, *(uint*)&h7);
                size_t base = (((size_t)br*18 + gg)*HBHW + gid0 + px)*2;
                g_u12v[base]     = lo;
                g_u12v[base + 1] = hi;
            }
        } else {
            for (int idx = tid; idx < 3*128; idx += 256) {
                int g3 = idx >> 7, px = idx & 127;
                int q = (nc - 6)*3 + g3;            // 0..8
                const float* ec = epi + (g3*16)*130 + px;
                size_t base = (((size_t)br*9 + q)*HBHW + gid0 + px)*4;
                #pragma unroll
                for (int w = 0; w < 4; w++)
                    g_u3v[base + w] = make_float4(ec[(4*w+0)*130], ec[(4*w+1)*130],
                                                  ec[(4*w+2)*130], ec[(4*w+3)*130]);
            }
        }
    }
}

// ---------------- K3: fused attention + final GEMM ----------------------
// 256 thr / 128 px: thr 0-127 = br0 attn, 128-255 = br1 attn.
// cat -> smem [chunk][px*36+c]; B staged into dead att region; 9-chunk GEMM.
#define AO_ATT_B 84992                       // float att[256*83]
#define AO_CAT_B 82944                       // half cat[9*128*36]
#define AO_TOTAL (AO_ATT_B + AO_CAT_B)       // 167936
__global__ void __launch_bounds__(256)
k_attn_out(const float* __restrict__ scale,
           const float* __restrict__ bo, float* __restrict__ out)
{
    extern __shared__ char smb[];
    float*  atm  = (float*)smb;
    __half* cats = (__half*)(smb + AO_ATT_B);
    __half* Bs   = (__half*)smb;             // reused after attn phase

    int tid = threadIdx.x;
    int pg = blockIdx.x*128;
    int bb = pg / HW;
    int p0 = pg - bb*HW;

    // ================= attention phase =================
    {
        int br  = tid >> 7;
        int lpx = tid & 127;
        int gid = pg + lpx;
        int p = p0 + lpx;
        int y = p / IMGW, x = p - y*IMGW;
        int shift = br ? 5 : 1;
        float sc = __ldg(&scale[br]);
        float* att = atm + tid*83;
        int cbase = br*144;

        int  gofs[9];
        bool inb[9];
        #pragma unroll
        for (int g = 0; g < 9; g++) {
            int yy = y + shift*c_dy[g];
            int xx = x + shift*c_dx[g];
            inb[g]  = ((unsigned)yy < (unsigned)IMGH) && ((unsigned)xx < (unsigned)IMGW);
            gofs[g] = shift*(c_dy[g]*IMGW + c_dx[g]);
        }

        // ---- Phase A: attention weights -> private smem ----
        {
            __half2 v1[9][8];
            #pragma unroll
            for (int g = 0; g < 9; g++) {
                if (inb[g]) {
                    size_t base = (((size_t)br*18 + g)*HBHW + gid + gofs[g])*2;
                    uint4 a = __ldg(&g_u12v[base]);
                    uint4 b = __ldg(&g_u12v[base + 1]);
                    v1[g][0] = *(__half2*)&a.x; v1[g][1] = *(__half2*)&a.y;
                    v1[g][2] = *(__half2*)&a.z; v1[g][3] = *(__half2*)&a.w;
                    v1[g][4] = *(__half2*)&b.x; v1[g][5] = *(__half2*)&b.y;
                    v1[g][6] = *(__half2*)&b.z; v1[g][7] = *(__half2*)&b.w;
                } else {
                    #pragma unroll
                    for (int c2 = 0; c2 < 8; c2++) v1[g][c2] = __half2half2(__float2half(0.f));
                }
            }

            #pragma unroll 1
            for (int pp = 0; pp < 9; pp++) {
                __half2 v2[8];
                if (inb[pp]) {
                    size_t base = (((size_t)br*18 + 9 + pp)*HBHW + gid + gofs[pp])*2;
                    uint4 a = __ldg(&g_u12v[base]);
                    uint4 b = __ldg(&g_u12v[base + 1]);
                    v2[0] = *(__half2*)&a.x; v2[1] = *(__half2*)&a.y;
                    v2[2] = *(__half2*)&a.z; v2[3] = *(__half2*)&a.w;
                    v2[4] = *(__half2*)&b.x; v2[5] = *(__half2*)&b.y;
                    v2[6] = *(__half2*)&b.z; v2[7] = *(__half2*)&b.w;
                } else {
                    #pragma unroll
                    for (int c2 = 0; c2 < 8; c2++) v2[c2] = __half2half2(__float2half(0.f));
                }

                float lg[9];
                #pragma unroll
                for (int q = 0; q < 9; q++) {
                    __half2 s = __hmul2(v2[0], v1[q][0]);
                    #pragma unroll
                    for (int c2 = 1; c2 < 8; c2++) s = __hfma2(v2[c2], v1[q][c2], s);
                    float2 f = __half22float2(s);
                    lg[q] = (f.x + f.y) * sc;
                }
                float m = lg[0];
                #pragma unroll
                for (int q = 1; q < 9; q++) m = fmaxf(m, lg[q]);
                float s = 0.f;
                float ex[9];
                #pragma unroll
                for (int q = 0; q < 9; q++) { ex[q] = __expf(lg[q] - m); s += ex[q]; }
                float inv = 1.f / s;
                #pragma unroll
                for (int q = 0; q < 9; q++) att[pp*9+q] = ex[q] * inv;
            }
        }

        // ---- Phase B: apply -> cat smem ----
        {
            float oa[5][16];
            #pragma unroll
            for (int pp = 0; pp < 5; pp++)
                #pragma unroll
                for (int c = 0; c < 16; c++) oa[pp][c] = 0.f;
            #pragma unroll 1
            for (int q = 0; q < 9; q++) {
                if (!inb[q]) continue;
                size_t base = (((size_t)br*9 + q)*HBHW + gid + gofs[q])*4;
                float v3[16];
                #pragma unroll
                for (int w = 0; w < 4; w++) {
                    float4 f = __ldg(&g_u3v[base + w]);
                    v3[4*w] = f.x; v3[4*w+1] = f.y; v3[4*w+2] = f.z; v3[4*w+3] = f.w;
                }
                #pragma unroll
                for (int pp = 0; pp < 5; pp++) {
                    float a = att[pp*9+q];
                    #pragma unroll
                    for (int c = 0; c < 16; c++) oa[pp][c] += a * v3[c];
                }
            }
            #pragma unroll
            for (int pp = 0; pp < 5; pp++)
                #pragma unroll
                for (int c2 = 0; c2 < 8; c2++) {
                    int ch = cbase + pp*16 + 2*c2;
                    *(__half2*)&cats[(ch >> 5)*4608 + lpx*36 + (ch & 31)]
                        = __floats2half2_rn(oa[pp][2*c2], oa[pp][2*c2+1]);
                }
        }
        {
            float oa[4][16];
            #pragma unroll
            for (int pp = 0; pp < 4; pp++)
                #pragma unroll
                for (int c = 0; c < 16; c++) oa[pp][c] = 0.f;
            #pragma unroll 1
            for (int q = 0; q < 9; q++) {
                if (!inb[q]) continue;
                size_t base = (((size_t)br*9 + q)*HBHW + gid + gofs[q])*4;
                float v3[16];
                #pragma unroll
                for (int w = 0; w < 4; w++) {
                    float4 f = __ldg(&g_u3v[base + w]);
                    v3[4*w] = f.x; v3[4*w+1] = f.y; v3[4*w+2] = f.z; v3[4*w+3] = f.w;
                }
                #pragma unroll
                for (int pp = 0; pp < 4; pp++) {
                    float a = att[(pp+5)*9+q];
                    #pragma unroll
                    for (int c = 0; c < 16; c++) oa[pp][c] += a * v3[c];
                }
            }
            #pragma unroll
            for (int pp = 0; pp < 4; pp++)
                #pragma unroll
                for (int c2 = 0; c2 < 8; c2++) {
                    int ch = cbase + (pp+5)*16 + 2*c2;
                    *(__half2*)&cats[(ch >> 5)*4608 + lpx*36 + (ch & 31)]
                        = __floats2half2_rn(oa[pp][2*c2], oa[pp][2*c2+1]);
                }
        }
    }
    __syncthreads();

    // ================= stage B weights into dead att region =================
    for (int j = tid; j < 18432; j += 256) {
        int o  = j / 144;
        int i2 = (j - o*144)*2;
        __half2 w = *(const __half2*)&g_woh[o*CCAT + i2];
        *(__half2*)&Bs[(i2 >> 5)*4608 + o*36 + (i2 & 31)] = w;
    }
    __syncthreads();

    // ================= GEMM phase (barrier-free) =================
    {
        int lane = tid & 31;
        int wid  = tid >> 5;
        int wm   = wid >> 1;
        int wn   = wid & 1;
        int g    = lane >> 2;
        int k0   = 2*(lane & 3);

        float acc[2][8][4];
        #pragma unroll
        for (int mt = 0; mt < 2; mt++)
            #pragma unroll
            for (int nt = 0; nt < 8; nt++)
                #pragma unroll
                for (int i = 0; i < 4; i++) acc[mt][nt][i] = 0.f;

        #pragma unroll 1
        for (int ch = 0; ch < 9; ch++) {
            const __half* Ah = cats + ch*4608;
            const __half* Bh = Bs   + ch*4608;
            #pragma unroll
            for (int ks = 0; ks < 32; ks += 16) {
                uint bh[8][2];
                #pragma unroll
                for (int nt = 0; nt < 8; nt++) {
                    int bbase = (wn*64 + nt*8 + g)*36 + ks + k0;
                    bh[nt][0] = lduh(&Bh[bbase]); bh[nt][1] = lduh(&Bh[bbase+8]);
                }
                #pragma unroll
                for (int mt = 0; mt < 2; mt++) {
                    int ab = (wm*32 + mt*16 + g)*36 + ks + k0;
                    uint ah0 = lduh(&Ah[ab]),      ah1 = lduh(&Ah[ab+8*36]);
                    uint ah2 = lduh(&Ah[ab+8]),    ah3 = lduh(&Ah[ab+8*36+8]);
                    #pragma unroll
                    for (int nt = 0; nt < 8; nt++)
                        mma16816(acc[mt][nt], ah0, ah1, ah2, ah3, bh[nt][0], bh[nt][1]);
                }
            }
        }

        float bv[16];
        #pragma unroll
        for (int nt = 0; nt < 8; nt++) {
            bv[2*nt]   = __ldg(&bo[wn*64 + nt*8 + 2*(lane & 3)]);
            bv[2*nt+1] = __ldg(&bo[wn*64 + nt*8 + 2*(lane & 3) + 1]);
        }
        float* ob = out + (size_t)bb*COUT*HW;
        #pragma unroll
        for (int mt = 0; mt < 2; mt++) {
            #pragma unroll
            for (int nt = 0; nt < 8; nt++) {
                #pragma unroll
                for (int i = 0; i < 4; i++) {
                    int o  = wn*64 + nt*8 + 2*(lane & 3) + (i & 1);
                    int px = p0 + wm*32 + mt*16 + (lane >> 2) + ((i >= 2) ? 8 : 0);
                    ob[(size_t)o*HW + px] = acc[mt][nt][i] + bv[2*nt + (i & 1)];
                }
            }
        }
    }
}

// ---------------- launcher ----------------
extern "C" void kernel_launch(void* const* d_in, const int* in_sizes, int n_in,
                              void* d_out, int out_size)
{
    const float* cen   = (const float*)d_in[0];
    const float* in_w0 = (const float*)d_in[1];
    const float* in_b0 = (const float*)d_in[2];
    const float* in_w1 = (const float*)d_in[3];
    const float* in_b1 = (const float*)d_in[4];
    const float* w1_0  = (const float*)d_in[5];
    const float* w2_0  = (const float*)d_in[6];
    const float* w3_0  = (const float*)d_in[7];
    const float* w1_1  = (const float*)d_in[8];
    const float* w2_1  = (const float*)d_in[9];
    const float* w3_1  = (const float*)d_in[10];
    const float* scale = (const float*)d_in[11];
    const float* out_w = (const float*)d_in[12];
    const float* out_b = (const float*)d_in[13];
    float* out = (float*)d_out;

    size_t cv_smem = (size_t)(A_PLANE + B_PLANE)*sizeof(__half);         // 42624 B
    size_t ug_smem = (size_t)(128*18 + 2*432*18)*sizeof(__half)
                   + (size_t)48*130*sizeof(float);                        // 60672 B
    cudaFuncSetAttribute(k_conv_mma, cudaFuncAttributeMaxDynamicSharedMemorySize,
                         (int)cv_smem);
    cudaFuncSetAttribute(k_ugemm, cudaFuncAttributeMaxDynamicSharedMemorySize,
                         (int)ug_smem);
    cudaFuncSetAttribute(k_attn_out, cudaFuncAttributeMaxDynamicSharedMemorySize,
                         AO_TOTAL);

    int prep_n = 10*16*256 + COUT*CCAT + 2*432*18;
    k_prep<<<(prep_n + 255)/256, 256>>>(in_w1, in_w0, out_w,
                                        w1_0, w2_0, w3_0, w1_1, w2_1, w3_1);
    k_conv_mma<<<576, 256, cv_smem>>>(cen, in_b0, in_b1);
    k_ugemm<<<HBHW/128, 256, ug_smem>>>(0);
    k_ugemm<<<HBHW/128, 256, ug_smem>>>(1);
    k_attn_out<<<HBHW/128, 256, AO_TOTAL>>>(scale, out_b, out);
}

// round 16
// speedup vs baseline: 1.0080x; 1.0080x over previous
#include <cuda_runtime.h>
#include <cuda_fp16.h>
#include <cstdint>

#define HB   4
#define CIN  256
#define HID  16
#define IMGH 192
#define IMGW 192
#define HW   (IMGH*IMGW)        // 36864
#define HBHW (HB*HW)            // 147456
#define COUT 128
#define CCAT 288

typedef unsigned int uint;

// ---------------- scratch (device globals; no allocation) ----------------
__device__ __half2 g_h2[2][(size_t)8*HBHW];      // h pairs [br][b*8+c2][HW]
__device__ __half2 g_cat2[(size_t)144*HBHW];     // cat pairs [b*144+cp][HW]
__device__ __half  g_wkh[10*16*256];             // conv taps [t][o][ci]
__device__ __half  g_woh[COUT*CCAT];             // out weights [o][i]
__device__ __half  g_ubwh[2*432*18];             // branch GEMM B hi (sgn folded)
__device__ __half  g_ubwl[2*432*18];
__device__ uint4   g_u12v[(size_t)2*18*HBHW*2];  // u1,u2 [br][grp][px][32B]
__device__ float4  g_u3v[(size_t)2*9*HBHW*4];    // u3    [br][q][px][64B]

__constant__ int c_dy[9] = {-1,-1,-1, 0, 1, 1, 1, 0, 0};
__constant__ int c_dx[9] = {-1, 0, 1, 1, 1, 0,-1,-1, 0};

__device__ __forceinline__ void h2split(float v, __half& h, __half& l)
{
    h = __float2half_rn(v);
    l = __float2half_rn(v - __half2float(h));
}
__device__ __forceinline__ uint lduh(const __half* p) { return *(const uint*)p; }

__device__ __forceinline__ void mma16816(float* d,
                                         uint a0, uint a1, uint a2, uint a3,
                                         uint b0, uint b1)
{
    asm volatile("mma.sync.aligned.m16n8k16.row.col.f32.f16.f16.f32 "
        "{%0,%1,%2,%3}, {%4,%5,%6,%7}, {%8,%9}, {%0,%1,%2,%3};"
        : "+f"(d[0]), "+f"(d[1]), "+f"(d[2]), "+f"(d[3])
        : "r"(a0), "r"(a1), "r"(a2), "r"(a3), "r"(b0), "r"(b1));
}

// ---------------- prep ----------------
__global__ void k_prep(const float* __restrict__ w3c,
                       const float* __restrict__ w1c,
                       const float* __restrict__ wo,
                       const float* __restrict__ w1_0, const float* __restrict__ w2_0,
                       const float* __restrict__ w3_0,
                       const float* __restrict__ w1_1, const float* __restrict__ w2_1,
                       const float* __restrict__ w3_1)
{
    int idx = blockIdx.x*256 + threadIdx.x;
    const int N1 = 10*16*256;
    const int N2 = COUT*CCAT;
    if (idx < N1) {
        int t  = idx >> 12;
        int o  = (idx >> 8) & 15;
        int ci = idx & 255;
        float v = (t < 9) ? w3c[(o*256 + ci)*9 + t] : w1c[o*256 + ci];
        g_wkh[idx] = __float2half_rn(v);
    } else if (idx < N1 + N2) {
        int j = idx - N1;
        g_woh[j] = __float2half_rn(wo[j]);
    } else if (idx < N1 + N2 + 2*432*18) {
        int j2 = idx - N1 - N2;
        int br = j2 / (432*18);
        int rem = j2 - br*(432*18);
        int n = rem / 18;
        int k = rem - n*18;
        int jj = n / 144;
        int g  = (n >> 4) % 9;
        int d  = n & 15;
        float v = 0.f;
        if (k < 16) {
            const float* src = (br == 0)
                ? ((jj == 0) ? w1_0 : (jj == 1) ? w2_0 : w3_0)
                : ((jj == 0) ? w1_1 : (jj == 1) ? w2_1 : w3_1);
            v = src[g*256 + d*16 + k];
            if (g < 8) v = -v;
        }
        __half h, l; h2split(v, h, l);
        g_ubwh[j2] = h; g_ubwl[j2] = l;
    }
}

// ---------------- K1: fused conv via HMMA, 1-term, half2 epilogue --------
#define A_PLANE 15552
#define B_PLANE 5760
__global__ void __launch_bounds__(256)
k_conv_mma(const float* __restrict__ cen,
           const float* __restrict__ b0v,
           const float* __restrict__ b1v)
{
    extern __shared__ __half smc[];
    __half* Ah = smc;
    __half* Bh = Ah + A_PLANE;

    int tid  = threadIdx.x;
    int lane = tid & 31;
    int wid  = tid >> 5;
    int y_l  = wid & 3;
    int xh   = wid >> 2;

    int bx = blockIdx.x % 3;
    int yt = (blockIdx.x / 3) % 48;
    int bb = blockIdx.x / 144;
    int x0 = bx*64, y0 = yt*4;

    const int tdy[10] = {-1,-1,-1, 0, 0, 0, 1, 1, 1, 0};
    const int tdx[10] = {-1, 0, 1,-1, 0, 1,-1, 0, 1, 0};

    float acc1[2][2][4];
    float acc0[2][2][4];
    #pragma unroll
    for (int mt = 0; mt < 2; mt++)
        #pragma unroll
        for (int nt = 0; nt < 2; nt++)
            #pragma unroll
            for (int i = 0; i < 4; i++) { acc1[mt][nt][i] = 0.f; acc0[mt][nt][i] = 0.f; }

    int g  = lane >> 2;
    int k0 = 2*(lane & 3);
    int e0 = ((y_l + 1)*72 + (xh*32 + g + 1))*36;

    for (int ci0 = 0; ci0 < CIN; ci0 += 32) {
        __syncthreads();
        for (int j = tid; j < 32*6*68; j += 256) {
            int sx = j % 68;
            int r2 = j / 68;
            int sy = r2 % 6;
            int ci = r2 / 6;
            int gy = y0 - 1 + sy, gx = x0 - 1 + sx;
            float v = 0.f;
            if ((unsigned)gy < (unsigned)IMGH && (unsigned)gx < (unsigned)IMGW)
                v = __ldg(&cen[((size_t)(bb*CIN + ci0 + ci))*HW + gy*IMGW + gx]);
            Ah[(sy*72 + sx)*36 + ci] = __float2half_rn(v);
        }
        for (int j = tid; j < 10*16*32; j += 256) {
            int ci = j & 31;
            int o  = (j >> 5) & 15;
            int t  = j >> 9;
            Bh[(t*16 + o)*36 + ci] = g_wkh[(t*16 + o)*256 + ci0 + ci];
        }
        __syncthreads();

        #pragma unroll 1
        for (int t = 0; t < 10; t++) {
            int aoff = (tdy[t]*72 + tdx[t])*36;
            #pragma unroll
            for (int ks = 0; ks < 32; ks += 16) {
                uint bh[2][2];
                #pragma unroll
                for (int nt = 0; nt < 2; nt++) {
                    int bbase = (t*16 + nt*8 + g)*36 + ks + k0;
                    bh[nt][0] = lduh(&Bh[bbase]);     bh[nt][1] = lduh(&Bh[bbase+8]);
                }
                #pragma unroll
                for (int mt = 0; mt < 2; mt++) {
                    int ab = e0 + aoff + mt*16*36 + ks + k0;
                    uint ah0 = lduh(&Ah[ab]),         ah1 = lduh(&Ah[ab+8*36]);
                    uint ah2 = lduh(&Ah[ab+8]),       ah3 = lduh(&Ah[ab+8*36+8]);
                    float (*acc)[4] = (t < 9) ? acc1[mt] : acc0[mt];
                    #pragma unroll
                    for (int nt = 0; nt < 2; nt++)
                        mma16816(acc[nt], ah0, ah1, ah2, ah3, bh[nt][0], bh[nt][1]);
                }
            }
        }
    }

    #pragma unroll
    for (int mt = 0; mt < 2; mt++) {
        #pragma unroll
        for (int nt = 0; nt < 2; nt++) {
            int c2 = nt*4 + (lane & 3);
            float bv0 = __ldg(&b1v[2*c2]), bv1 = __ldg(&b1v[2*c2+1]);
            float av0 = __ldg(&b0v[2*c2]), av1 = __ldg(&b0v[2*c2+1]);
            int gx = x0 + xh*32 + mt*16 + (lane >> 2);
            int gy = y0 + y_l;
            size_t ofs = ((size_t)(bb*8 + c2))*HW + gy*IMGW + gx;
            g_h2[1][ofs]     = __floats2half2_rn(acc1[mt][nt][0]+bv0, acc1[mt][nt][1]+bv1);
            g_h2[1][ofs + 8] = __floats2half2_rn(acc1[mt][nt][2]+bv0, acc1[mt][nt][3]+bv1);
            g_h2[0][ofs]     = __floats2half2_rn(acc0[mt][nt][0]+av0, acc0[mt][nt][1]+av1);
            g_h2[0][ofs + 8] = __floats2half2_rn(acc0[mt][nt][2]+av0, acc0[mt][nt][3]+av1);
        }
    }
}

// ---------------- K2: u-GEMM, 2-term, warp-local epilogue ----------------
// transpose is warp-local (each warp owns 16 px x 48 cols) -> no CTA barriers
// in the nc loop; per-warp 48x17 epi tile + __syncwarp only.
__global__ void __launch_bounds__(256)
k_ugemm(int br)
{
    extern __shared__ __half smu[];
    __half* Ah = smu;                        // 128*18
    __half* Bh = Ah + 128*18;                // 432*18
    __half* Bl = Bh + 432*18;
    float*  epi = (float*)(Bl + 432*18);     // 8 warps * 48*17

    int tid  = threadIdx.x;
    int lane = tid & 31;
    int wid  = tid >> 5;

    int gid0 = blockIdx.x*128;
    int bb = gid0 / HW;
    int p0 = gid0 - bb*HW;

    for (int idx = tid; idx < 432*18; idx += 256) {
        Bh[idx] = g_ubwh[br*432*18 + idx];
        Bl[idx] = g_ubwl[br*432*18 + idx];
    }
    for (int idx = tid; idx < 128*8; idx += 256) {
        int c2 = idx >> 7, px = idx & 127;
        __half2 v = g_h2[br][((size_t)(bb*8 + c2))*HW + p0 + px];
        *(__half2*)&Ah[px*18 + 2*c2] = v;
    }
    __syncthreads();

    int m0 = wid*16;
    int gr = lane >> 2;
    int k0 = 2*(lane & 3);
    int ab = (m0 + gr)*18 + k0;
    uint ah0 = lduh(&Ah[ab]),      ah1 = lduh(&Ah[ab + 8*18]);
    uint ah2 = lduh(&Ah[ab+8]),    ah3 = lduh(&Ah[ab + 8*18 + 8]);

    float* wepi = epi + wid*816;             // 48 cols x 17 pad

    for (int nc = 0; nc < 9; nc++) {
        float acc[6][4];
        #pragma unroll
        for (int nt = 0; nt < 6; nt++)
            #pragma unroll
            for (int i = 0; i < 4; i++) acc[nt][i] = 0.f;

        #pragma unroll
        for (int nt = 0; nt < 6; nt++) {
            int n8 = (nc*6 + nt)*8;
            int bbase = (n8 + gr)*18 + k0;
            uint bh0 = lduh(&Bh[bbase]), bh1 = lduh(&Bh[bbase+8]);
            uint bl0 = lduh(&Bl[bbase]), bl1 = lduh(&Bl[bbase+8]);
            mma16816(acc[nt], ah0, ah1, ah2, ah3, bh0, bh1);
            mma16816(acc[nt], ah0, ah1, ah2, ah3, bl0, bl1);
        }
        #pragma unroll
        for (int nt = 0; nt < 6; nt++) {
            #pragma unroll
            for (int i = 0; i < 4; i++) {
                int col  = nt*8 + 2*(lane & 3) + (i & 1);
                int rowl = gr + ((i >= 2) ? 8 : 0);
                wepi[col*17 + rowl] = acc[nt][i];
            }
        }
        __syncwarp();
        if (nc < 6) {
            #pragma unroll
            for (int e = lane; e < 96; e += 32) {
                int g3 = e >> 5, rem = e & 31;
                int px = rem >> 1, h = rem & 1;
                const float* ec = wepi + (g3*16 + h*8)*17 + px;
                __half2 h0 = __floats2half2_rn(ec[0*17], ec[1*17]);
                __half2 h1 = __floats2half2_rn(ec[2*17], ec[3*17]);
                __half2 h2 = __floats2half2_rn(ec[4*17], ec[5*17]);
                __half2 h3 = __floats2half2_rn(ec[6*17], ec[7*17]);
                uint4 v = make_uint4(*(uint*)&h0, *(uint*)&h1, *(uint*)&h2, *(uint*)&h3);
                size_t base = (((size_t)br*18 + nc*3 + g3)*HBHW + gid0 + m0 + px)*2 + h;
                g_u12v[base] = v;
            }
        } else {
            #pragma unroll
            for (int e = lane; e < 192; e += 32) {
                int g3 = e >> 6, rem = e & 63;
                int px = rem >> 2, w = rem & 3;
                const float* ec = wepi + (g3*16 + 4*w)*17 + px;
                float4 f = make_float4(ec[0], ec[17], ec[34], ec[51]);
                size_t base = (((size_t)br*9 + (nc-6)*3 + g3)*HBHW + gid0 + m0 + px)*4 + w;
                g_u3v[base] = f;
            }
        }
        __syncwarp();
    }
}

// ---------------- K3: gather + attention, vectorized ---------------------
#define ATTP 83
__global__ void __launch_bounds__(128)
k_attn(int br, int shift, const float* __restrict__ scale, int sidx, int cb2)
{
    extern __shared__ float atm[];               // 128 * ATTP
    int tid = threadIdx.x;
    int gid = blockIdx.x*128 + tid;
    int bb = gid / HW, p = gid - bb*HW;
    int y = p / IMGW, x = p - y*IMGW;

    float sc = __ldg(&scale[sidx]);
    float* att = atm + tid*ATTP;

    int  gofs[9];
    bool inb[9];
    #pragma unroll
    for (int g = 0; g < 9; g++) {
        int yy = y + shift*c_dy[g];
        int xx = x + shift*c_dx[g];
        inb[g]  = ((unsigned)yy < (unsigned)IMGH) && ((unsigned)xx < (unsigned)IMGW);
        gofs[g] = shift*(c_dy[g]*IMGW + c_dx[g]);
    }

    // ---- Phase A: attention weights -> private smem ----
    {
        __half2 v1[9][8];
        #pragma unroll
        for (int g = 0; g < 9; g++) {
            if (inb[g]) {
                size_t base = (((size_t)br*18 + g)*HBHW + gid + gofs[g])*2;
                uint4 a = __ldg(&g_u12v[base]);
                uint4 b = __ldg(&g_u12v[base + 1]);
                v1[g][0] = *(__half2*)&a.x; v1[g][1] = *(__half2*)&a.y;
                v1[g][2] = *(__half2*)&a.z; v1[g][3] = *(__half2*)&a.w;
                v1[g][4] = *(__half2*)&b.x; v1[g][5] = *(__half2*)&b.y;
                v1[g][6] = *(__half2*)&b.z; v1[g][7] = *(__half2*)&b.w;
            } else {
                #pragma unroll
                for (int c2 = 0; c2 < 8; c2++) v1[g][c2] = __half2half2(__float2half(0.f));
            }
        }

        #pragma unroll 1
        for (int pp = 0; pp < 9; pp++) {
            __half2 v2[8];
            if (inb[pp]) {
                size_t base = (((size_t)br*18 + 9 + pp)*HBHW + gid + gofs[pp])*2;
                uint4 a = __ldg(&g_u12v[base]);
                uint4 b = __ldg(&g_u12v[base + 1]);
                v2[0] = *(__half2*)&a.x; v2[1] = *(__half2*)&a.y;
                v2[2] = *(__half2*)&a.z; v2[3] = *(__half2*)&a.w;
                v2[4] = *(__half2*)&b.x; v2[5] = *(__half2*)&b.y;
                v2[6] = *(__half2*)&b.z; v2[7] = *(__half2*)&b.w;
            } else {
                #pragma unroll
                for (int c2 = 0; c2 < 8; c2++) v2[c2] = __half2half2(__float2half(0.f));
            }

            float lg[9];
            #pragma unroll
            for (int q = 0; q < 9; q++) {
                __half2 s = __hmul2(v2[0], v1[q][0]);
                #pragma unroll
                for (int c2 = 1; c2 < 8; c2++) s = __hfma2(v2[c2], v1[q][c2], s);
                float2 f = __half22float2(s);
                lg[q] = (f.x + f.y) * sc;
            }
            float m = lg[0];
            #pragma unroll
            for (int q = 1; q < 9; q++) m = fmaxf(m, lg[q]);
            float s = 0.f;
            float ex[9];
            #pragma unroll
            for (int q = 0; q < 9; q++) { ex[q] = __expf(lg[q] - m); s += ex[q]; }
            float inv = 1.f / s;
            #pragma unroll
            for (int q = 0; q < 9; q++) att[pp*9+q] = ex[q] * inv;
        }
    }

    __half2* catb = g_cat2 + (size_t)(bb*144 + cb2)*HW + p;

    // ---- Phase B: two register passes, v3 via float4 ----
    {
        float oa[5][16];
        #pragma unroll
        for (int pp = 0; pp < 5; pp++)
            #pragma unroll
            for (int c = 0; c < 16; c++) oa[pp][c] = 0.f;
        #pragma unroll 1
        for (int q = 0; q < 9; q++) {
            if (!inb[q]) continue;
            size_t base = (((size_t)br*9 + q)*HBHW + gid + gofs[q])*4;
            float v3[16];
            #pragma unroll
            for (int w = 0; w < 4; w++) {
                float4 f = __ldg(&g_u3v[base + w]);
                v3[4*w] = f.x; v3[4*w+1] = f.y; v3[4*w+2] = f.z; v3[4*w+3] = f.w;
            }
            #pragma unroll
            for (int pp = 0; pp < 5; pp++) {
                float a = att[pp*9+q];
                #pragma unroll
                for (int c = 0; c < 16; c++) oa[pp][c] += a * v3[c];
            }
        }
        #pragma unroll
        for (int pp = 0; pp < 5; pp++)
            #pragma unroll
            for (int c2 = 0; c2 < 8; c2++)
                catb[(size_t)(pp*8 + c2)*HW] = __floats2half2_rn(oa[pp][2*c2], oa[pp][2*c2+1]);
    }
    {
        float oa[4][16];
        #pragma unroll
        for (int pp = 0; pp < 4; pp++)
            #pragma unroll
            for (int c = 0; c < 16; c++) oa[pp][c] = 0.f;
        #pragma unroll 1
        for (int q = 0; q < 9; q++) {
            if (!inb[q]) continue;
            size_t base = (((size_t)br*9 + q)*HBHW + gid + gofs[q])*4;
            float v3[16];
            #pragma unroll
            for (int w = 0; w < 4; w++) {
                float4 f = __ldg(&g_u3v[base + w]);
                v3[4*w] = f.x; v3[4*w+1] = f.y; v3[4*w+2] = f.z; v3[4*w+3] = f.w;
            }
            #pragma unroll
            for (int pp = 0; pp < 4; pp++) {
                float a = att[(pp+5)*9+q];
                #pragma unroll
                for (int c = 0; c < 16; c++) oa[pp][c] += a * v3[c];
            }
        }
        #pragma unroll
        for (int pp = 0; pp < 4; pp++)
            #pragma unroll
            for (int c2 = 0; c2 < 8; c2++)
                catb[(size_t)((pp+5)*8 + c2)*HW] = __floats2half2_rn(oa[pp][2*c2], oa[pp][2*c2+1]);
    }
}

// ---------------- K4: final 1x1 conv via HMMA, 1-term, half2 input -------
__global__ void __launch_bounds__(256)
k_out_mma(const float* __restrict__ bo, float* __restrict__ out)
{
    __shared__ __half Ah[128*36], Bh[128*36];

    int tid  = threadIdx.x;
    int lane = tid & 31;
    int wid  = tid >> 5;
    int wm   = wid >> 1;
    int wn   = wid & 1;

    int pg = blockIdx.x*128;
    int bb = pg / HW;
    int p0 = pg - bb*HW;

    float acc[2][8][4];
    #pragma unroll
    for (int mt = 0; mt < 2; mt++)
        #pragma unroll
        for (int nt = 0; nt < 8; nt++)
            #pragma unroll
            for (int i = 0; i < 4; i++) acc[mt][nt][i] = 0.f;

    int g  = lane >> 2;
    int k0 = 2*(lane & 3);

    for (int i0 = 0; i0 < CCAT; i0 += 32) {
        int cp0 = i0 >> 1;
        __syncthreads();
        for (int idx = tid; idx < 16*128; idx += 256) {
            int c2 = idx >> 7, px = idx & 127;
            __half2 v = g_cat2[(size_t)(bb*144 + cp0 + c2)*HW + p0 + px];
            *(__half2*)&Ah[px*36 + 2*c2] = v;
        }
        {
            int ch = tid & 31;
            int o0 = tid >> 5;
            for (int o = o0; o < COUT; o += 8)
                Bh[o*36 + ch] = g_woh[o*CCAT + i0 + ch];
        }
        __syncthreads();

        #pragma unroll
        for (int ks = 0; ks < 32; ks += 16) {
            uint bh[8][2];
            #pragma unroll
            for (int nt = 0; nt < 8; nt++) {
                int bbase = (wn*64 + nt*8 + g)*36 + ks + k0;
                bh[nt][0] = lduh(&Bh[bbase]); bh[nt][1] = lduh(&Bh[bbase+8]);
            }
            #pragma unroll
            for (int mt = 0; mt < 2; mt++) {
                int ab = (wm*32 + mt*16 + g)*36 + ks + k0;
                uint ah0 = lduh(&Ah[ab]),      ah1 = lduh(&Ah[ab+8*36]);
                uint ah2 = lduh(&Ah[ab+8]),    ah3 = lduh(&Ah[ab+8*36+8]);
                #pragma unroll
                for (int nt = 0; nt < 8; nt++)
                    mma16816(acc[mt][nt], ah0, ah1, ah2, ah3, bh[nt][0], bh[nt][1]);
            }
        }
    }

    float* ob = out + (size_t)bb*COUT*HW;
    #pragma unroll
    for (int mt = 0; mt < 2; mt++) {
        #pragma unroll
        for (int nt = 0; nt < 8; nt++) {
            #pragma unroll
            for (int i = 0; i < 4; i++) {
                int o  = wn*64 + nt*8 + 2*(lane & 3) + (i & 1);
                int px = p0 + wm*32 + mt*16 + (lane >> 2) + ((i >= 2) ? 8 : 0);
                ob[(size_t)o*HW + px] = acc[mt][nt][i] + __ldg(&bo[o]);
            }
        }
    }
}

// ---------------- launcher ----------------
extern "C" void kernel_launch(void* const* d_in, const int* in_sizes, int n_in,
                              void* d_out, int out_size)
{
    const float* cen   = (const float*)d_in[0];
    const float* in_w0 = (const float*)d_in[1];
    const float* in_b0 = (const float*)d_in[2];
    const float* in_w1 = (const float*)d_in[3];
    const float* in_b1 = (const float*)d_in[4];
    const float* w1_0  = (const float*)d_in[5];
    const float* w2_0  = (const float*)d_in[6];
    const float* w3_0  = (const float*)d_in[7];
    const float* w1_1  = (const float*)d_in[8];
    const float* w2_1  = (const float*)d_in[9];
    const float* w3_1  = (const float*)d_in[10];
    const float* scale = (const float*)d_in[11];
    const float* out_w = (const float*)d_in[12];
    const float* out_b = (const float*)d_in[13];
    float* out = (float*)d_out;

    size_t cv_smem = (size_t)(A_PLANE + B_PLANE)*sizeof(__half);         // 42624 B
    size_t ug_smem = (size_t)(128*18 + 2*432*18)*sizeof(__half)
                   + (size_t)8*816*sizeof(float);                         // 61824 B
    size_t at_smem = (size_t)128*ATTP*sizeof(float);                      // 42496 B
    cudaFuncSetAttribute(k_conv_mma, cudaFuncAttributeMaxDynamicSharedMemorySize,
                         (int)cv_smem);
    cudaFuncSetAttribute(k_ugemm, cudaFuncAttributeMaxDynamicSharedMemorySize,
                         (int)ug_smem);
    cudaFuncSetAttribute(k_attn, cudaFuncAttributeMaxDynamicSharedMemorySize,
                         (int)at_smem);

    int prep_n = 10*16*256 + COUT*CCAT + 2*432*18;
    k_prep<<<(prep_n + 255)/256, 256>>>(in_w1, in_w0, out_w,
                                        w1_0, w2_0, w3_0, w1_1, w2_1, w3_1);
    k_conv_mma<<<576, 256, cv_smem>>>(cen, in_b0, in_b1);
    k_ugemm<<<HBHW/128, 256, ug_smem>>>(0);
    k_ugemm<<<HBHW/128, 256, ug_smem>>>(1);
    k_attn<<<HBHW/128, 128, at_smem>>>(0, 1, scale, 0, 0);
    k_attn<<<HBHW/128, 128, at_smem>>>(1, 5, scale, 1, 72);
    k_out_mma<<<HBHW/128, 256>>>(out_b, out);
}

// round 17
// speedup vs baseline: 1.0440x; 1.0358x over previous
#include <cuda_runtime.h>
#include <cuda_fp16.h>
#include <cstdint>

#define HB   4
#define CIN  256
#define HID  16
#define IMGH 192
#define IMGW 192
#define HW   (IMGH*IMGW)        // 36864
#define HBHW (HB*HW)            // 147456
#define COUT 128
#define CCAT 288

typedef unsigned int uint;

// ---------------- scratch (device globals; no allocation) ----------------
__device__ __half2 g_h2[2][(size_t)8*HBHW];      // h pairs [br][b*8+c2][HW]
__device__ __half2 g_cat2[(size_t)144*HBHW];     // cat pairs [b*144+cp][HW]
__device__ __half  g_wkh[10*16*256];             // conv taps [t][o][ci]
__device__ __half  g_woh[COUT*CCAT];             // out weights [o][i]
__device__ __half  g_ubwh[2*432*18];             // branch GEMM B hi (sgn folded)
__device__ __half  g_ubwl[2*432*18];
__device__ uint4   g_u12v[(size_t)2*18*HBHW*2];  // u1,u2 [br][grp][px][32B]
__device__ float4  g_u3v[(size_t)2*9*HBHW*4];    // u3    [br][q][px][64B]

__constant__ int c_dy[9] = {-1,-1,-1, 0, 1, 1, 1, 0, 0};
__constant__ int c_dx[9] = {-1, 0, 1, 1, 1, 0,-1,-1, 0};

__device__ __forceinline__ void h2split(float v, __half& h, __half& l)
{
    h = __float2half_rn(v);
    l = __float2half_rn(v - __half2float(h));
}
__device__ __forceinline__ uint lduh(const __half* p) { return *(const uint*)p; }

__device__ __forceinline__ void mma16816(float* d,
                                         uint a0, uint a1, uint a2, uint a3,
                                         uint b0, uint b1)
{
    asm volatile("mma.sync.aligned.m16n8k16.row.col.f32.f16.f16.f32 "
        "{%0,%1,%2,%3}, {%4,%5,%6,%7}, {%8,%9}, {%0,%1,%2,%3};"
        : "+f"(d[0]), "+f"(d[1]), "+f"(d[2]), "+f"(d[3])
        : "r"(a0), "r"(a1), "r"(a2), "r"(a3), "r"(b0), "r"(b1));
}

// ---------------- prep ----------------
__global__ void k_prep(const float* __restrict__ w3c,
                       const float* __restrict__ w1c,
                       const float* __restrict__ wo,
                       const float* __restrict__ w1_0, const float* __restrict__ w2_0,
                       const float* __restrict__ w3_0,
                       const float* __restrict__ w1_1, const float* __restrict__ w2_1,
                       const float* __restrict__ w3_1)
{
    int idx = blockIdx.x*256 + threadIdx.x;
    const int N1 = 10*16*256;
    const int N2 = COUT*CCAT;
    if (idx < N1) {
        int t  = idx >> 12;
        int o  = (idx >> 8) & 15;
        int ci = idx & 255;
        float v = (t < 9) ? w3c[(o*256 + ci)*9 + t] : w1c[o*256 + ci];
        g_wkh[idx] = __float2half_rn(v);
    } else if (idx < N1 + N2) {
        int j = idx - N1;
        g_woh[j] = __float2half_rn(wo[j]);
    } else if (idx < N1 + N2 + 2*432*18) {
        int j2 = idx - N1 - N2;
        int br = j2 / (432*18);
        int rem = j2 - br*(432*18);
        int n = rem / 18;
        int k = rem - n*18;
        int jj = n / 144;
        int g  = (n >> 4) % 9;
        int d  = n & 15;
        float v = 0.f;
        if (k < 16) {
            const float* src = (br == 0)
                ? ((jj == 0) ? w1_0 : (jj == 1) ? w2_0 : w3_0)
                : ((jj == 0) ? w1_1 : (jj == 1) ? w2_1 : w3_1);
            v = src[g*256 + d*16 + k];
            if (g < 8) v = -v;
        }
        __half h, l; h2split(v, h, l);
        g_ubwh[j2] = h; g_ubwl[j2] = l;
    }
}

// ---------------- K1: fused conv via HMMA, 1-term, half2 epilogue --------
#define A_PLANE 15552
#define B_PLANE 5760
__global__ void __launch_bounds__(256)
k_conv_mma(const float* __restrict__ cen,
           const float* __restrict__ b0v,
           const float* __restrict__ b1v)
{
    extern __shared__ __half smc[];
    __half* Ah = smc;
    __half* Bh = Ah + A_PLANE;

    int tid  = threadIdx.x;
    int lane = tid & 31;
    int wid  = tid >> 5;
    int y_l  = wid & 3;
    int xh   = wid >> 2;

    int bx = blockIdx.x % 3;
    int yt = (blockIdx.x / 3) % 48;
    int bb = blockIdx.x / 144;
    int x0 = bx*64, y0 = yt*4;

    const int tdy[10] = {-1,-1,-1, 0, 0, 0, 1, 1, 1, 0};
    const int tdx[10] = {-1, 0, 1,-1, 0, 1,-1, 0, 1, 0};

    float acc1[2][2][4];
    float acc0[2][2][4];
    #pragma unroll
    for (int mt = 0; mt < 2; mt++)
        #pragma unroll
        for (int nt = 0; nt < 2; nt++)
            #pragma unroll
            for (int i = 0; i < 4; i++) { acc1[mt][nt][i] = 0.f; acc0[mt][nt][i] = 0.f; }

    int g  = lane >> 2;
    int k0 = 2*(lane & 3);
    int e0 = ((y_l + 1)*72 + (xh*32 + g + 1))*36;

    for (int ci0 = 0; ci0 < CIN; ci0 += 32) {
        __syncthreads();
        for (int j = tid; j < 32*6*68; j += 256) {
            int sx = j % 68;
            int r2 = j / 68;
            int sy = r2 % 6;
            int ci = r2 / 6;
            int gy = y0 - 1 + sy, gx = x0 - 1 + sx;
            float v = 0.f;
            if ((unsigned)gy < (unsigned)IMGH && (unsigned)gx < (unsigned)IMGW)
                v = __ldg(&cen[((size_t)(bb*CIN + ci0 + ci))*HW + gy*IMGW + gx]);
            Ah[(sy*72 + sx)*36 + ci] = __float2half_rn(v);
        }
        for (int j = tid; j < 10*16*32; j += 256) {
            int ci = j & 31;
            int o  = (j >> 5) & 15;
            int t  = j >> 9;
            Bh[(t*16 + o)*36 + ci] = g_wkh[(t*16 + o)*256 + ci0 + ci];
        }
        __syncthreads();

        #pragma unroll 1
        for (int t = 0; t < 10; t++) {
            int aoff = (tdy[t]*72 + tdx[t])*36;
            #pragma unroll
            for (int ks = 0; ks < 32; ks += 16) {
                uint bh[2][2];
                #pragma unroll
                for (int nt = 0; nt < 2; nt++) {
                    int bbase = (t*16 + nt*8 + g)*36 + ks + k0;
                    bh[nt][0] = lduh(&Bh[bbase]);     bh[nt][1] = lduh(&Bh[bbase+8]);
                }
                #pragma unroll
                for (int mt = 0; mt < 2; mt++) {
                    int ab = e0 + aoff + mt*16*36 + ks + k0;
                    uint ah0 = lduh(&Ah[ab]),         ah1 = lduh(&Ah[ab+8*36]);
                    uint ah2 = lduh(&Ah[ab+8]),       ah3 = lduh(&Ah[ab+8*36+8]);
                    float (*acc)[4] = (t < 9) ? acc1[mt] : acc0[mt];
                    #pragma unroll
                    for (int nt = 0; nt < 2; nt++)
                        mma16816(acc[nt], ah0, ah1, ah2, ah3, bh[nt][0], bh[nt][1]);
                }
            }
        }
    }

    #pragma unroll
    for (int mt = 0; mt < 2; mt++) {
        #pragma unroll
        for (int nt = 0; nt < 2; nt++) {
            int c2 = nt*4 + (lane & 3);
            float bv0 = __ldg(&b1v[2*c2]), bv1 = __ldg(&b1v[2*c2+1]);
            float av0 = __ldg(&b0v[2*c2]), av1 = __ldg(&b0v[2*c2+1]);
            int gx = x0 + xh*32 + mt*16 + (lane >> 2);
            int gy = y0 + y_l;
            size_t ofs = ((size_t)(bb*8 + c2))*HW + gy*IMGW + gx;
            g_h2[1][ofs]     = __floats2half2_rn(acc1[mt][nt][0]+bv0, acc1[mt][nt][1]+bv1);
            g_h2[1][ofs + 8] = __floats2half2_rn(acc1[mt][nt][2]+bv0, acc1[mt][nt][3]+bv1);
            g_h2[0][ofs]     = __floats2half2_rn(acc0[mt][nt][0]+av0, acc0[mt][nt][1]+av1);
            g_h2[0][ofs + 8] = __floats2half2_rn(acc0[mt][nt][2]+av0, acc0[mt][nt][3]+av1);
        }
    }
}

// ---------------- K2: u-GEMM, merged branches, 1-term u12 / 2-term u3 ----
// grid (HBHW/128, 2); br = blockIdx.y. CTA-wide padded epi (R12 form).
__global__ void __launch_bounds__(256)
k_ugemm()
{
    extern __shared__ __half smu[];
    __half* Ah = smu;                    // 128*18
    __half* Bh = Ah + 128*18;            // 432*18
    __half* Bl = Bh + 432*18;            // 144*18 (u3 cols only)
    float*  epi = (float*)(Bl + 144*18); // 48*130

    int tid  = threadIdx.x;
    int lane = tid & 31;
    int wid  = tid >> 5;
    int br   = blockIdx.y;

    int gid0 = blockIdx.x*128;
    int bb = gid0 / HW;
    int p0 = gid0 - bb*HW;

    for (int idx = tid; idx < 432*18; idx += 256)
        Bh[idx] = g_ubwh[br*432*18 + idx];
    for (int idx = tid; idx < 144*18; idx += 256)
        Bl[idx] = g_ubwl[br*432*18 + 288*18 + idx];
    for (int idx = tid; idx < 128*8; idx += 256) {
        int c2 = idx >> 7, px = idx & 127;
        __half2 v = g_h2[br][((size_t)(bb*8 + c2))*HW + p0 + px];
        *(__half2*)&Ah[px*18 + 2*c2] = v;
    }
    __syncthreads();

    int m0 = wid*16;
    int gr = lane >> 2;
    int k0 = 2*(lane & 3);
    int ab = (m0 + gr)*18 + k0;
    uint ah0 = lduh(&Ah[ab]),      ah1 = lduh(&Ah[ab + 8*18]);
    uint ah2 = lduh(&Ah[ab+8]),    ah3 = lduh(&Ah[ab + 8*18 + 8]);

    for (int nc = 0; nc < 9; nc++) {
        float acc[6][4];
        #pragma unroll
        for (int nt = 0; nt < 6; nt++)
            #pragma unroll
            for (int i = 0; i < 4; i++) acc[nt][i] = 0.f;

        if (nc < 6) {
            #pragma unroll
            for (int nt = 0; nt < 6; nt++) {
                int n8 = (nc*6 + nt)*8;
                int bbase = (n8 + gr)*18 + k0;
                uint bh0 = lduh(&Bh[bbase]), bh1 = lduh(&Bh[bbase+8]);
                mma16816(acc[nt], ah0, ah1, ah2, ah3, bh0, bh1);
            }
        } else {
            #pragma unroll
            for (int nt = 0; nt < 6; nt++) {
                int n8 = (nc*6 + nt)*8;
                int bbase = (n8 + gr)*18 + k0;
                int lbase = (n8 - 288 + gr)*18 + k0;
                uint bh0 = lduh(&Bh[bbase]), bh1 = lduh(&Bh[bbase+8]);
                uint bl0 = lduh(&Bl[lbase]), bl1 = lduh(&Bl[lbase+8]);
                mma16816(acc[nt], ah0, ah1, ah2, ah3, bh0, bh1);
                mma16816(acc[nt], ah0, ah1, ah2, ah3, bl0, bl1);
            }
        }
        __syncthreads();
        #pragma unroll
        for (int nt = 0; nt < 6; nt++) {
            #pragma unroll
            for (int i = 0; i < 4; i++) {
                int col = nt*8 + 2*(lane & 3) + (i & 1);
                int row = m0 + gr + ((i >= 2) ? 8 : 0);
                epi[col*130 + row] = acc[nt][i];
            }
        }
        __syncthreads();
        if (nc < 6) {
            for (int idx = tid; idx < 3*128; idx += 256) {
                int g3 = idx >> 7, px = idx & 127;
                int gg = nc*3 + g3;                 // 0..17 (u1 then u2)
                const float* ec = epi + (g3*16)*130 + px;
                __half2 h0 = __floats2half2_rn(ec[0*130],  ec[1*130]);
                __half2 h1 = __floats2half2_rn(ec[2*130],  ec[3*130]);
                __half2 h2 = __floats2half2_rn(ec[4*130],  ec[5*130]);
                __half2 h3 = __floats2half2_rn(ec[6*130],  ec[7*130]);
                __half2 h4 = __floats2half2_rn(ec[8*130],  ec[9*130]);
                __half2 h5 = __floats2half2_rn(ec[10*130], ec[11*130]);
                __half2 h6 = __floats2half2_rn(ec[12*130], ec[13*130]);
                __half2 h7 = __floats2half2_rn(ec[14*130], ec[15*130]);
                uint4 lo = make_uint4(*(uint*)&h0, *(uint*)&h1, *(uint*)&h2, *(uint*)&h3);
                uint4 hi = make_uint4(*(uint*)&h4, *(uint*)&h5, *(uint*)&h6, *(uint*)&h7);
                size_t base = (((size_t)br*18 + gg)*HBHW + gid0 + px)*2;
                g_u12v[base]     = lo;
                g_u12v[base + 1] = hi;
            }
        } else {
            for (int idx = tid; idx < 3*128; idx += 256) {
                int g3 = idx >> 7, px = idx & 127;
                int q = (nc - 6)*3 + g3;            // 0..8
                const float* ec = epi + (g3*16)*130 + px;
                size_t base = (((size_t)br*9 + q)*HBHW + gid0 + px)*4;
                #pragma unroll
                for (int w = 0; w < 4; w++)
                    g_u3v[base + w] = make_float4(ec[(4*w+0)*130], ec[(4*w+1)*130],
                                                  ec[(4*w+2)*130], ec[(4*w+3)*130]);
            }
        }
    }
}

// ---------------- K3: gather + attention, vectorized ---------------------
#define ATTP 83
__global__ void __launch_bounds__(128)
k_attn(int br, int shift, const float* __restrict__ scale, int sidx, int cb2)
{
    extern __shared__ float atm[];               // 128 * ATTP
    int tid = threadIdx.x;
    int gid = blockIdx.x*128 + tid;
    int bb = gid / HW, p = gid - bb*HW;
    int y = p / IMGW, x = p - y*IMGW;

    float sc = __ldg(&scale[sidx]);
    float* att = atm + tid*ATTP;

    int  gofs[9];
    bool inb[9];
    #pragma unroll
    for (int g = 0; g < 9; g++) {
        int yy = y + shift*c_dy[g];
        int xx = x + shift*c_dx[g];
        inb[g]  = ((unsigned)yy < (unsigned)IMGH) && ((unsigned)xx < (unsigned)IMGW);
        gofs[g] = shift*(c_dy[g]*IMGW + c_dx[g]);
    }

    // ---- Phase A: attention weights -> private smem ----
    {
        __half2 v1[9][8];
        #pragma unroll
        for (int g = 0; g < 9; g++) {
            if (inb[g]) {
                size_t base = (((size_t)br*18 + g)*HBHW + gid + gofs[g])*2;
                uint4 a = __ldg(&g_u12v[base]);
                uint4 b = __ldg(&g_u12v[base + 1]);
                v1[g][0] = *(__half2*)&a.x; v1[g][1] = *(__half2*)&a.y;
                v1[g][2] = *(__half2*)&a.z; v1[g][3] = *(__half2*)&a.w;
                v1[g][4] = *(__half2*)&b.x; v1[g][5] = *(__half2*)&b.y;
                v1[g][6] = *(__half2*)&b.z; v1[g][7] = *(__half2*)&b.w;
            } else {
                #pragma unroll
                for (int c2 = 0; c2 < 8; c2++) v1[g][c2] = __half2half2(__float2half(0.f));
            }
        }

        #pragma unroll 1
        for (int pp = 0; pp < 9; pp++) {
            __half2 v2[8];
            if (inb[pp]) {
                size_t base = (((size_t)br*18 + 9 + pp)*HBHW + gid + gofs[pp])*2;
                uint4 a = __ldg(&g_u12v[base]);
                uint4 b = __ldg(&g_u12v[base + 1]);
                v2[0] = *(__half2*)&a.x; v2[1] = *(__half2*)&a.y;
                v2[2] = *(__half2*)&a.z; v2[3] = *(__half2*)&a.w;
                v2[4] = *(__half2*)&b.x; v2[5] = *(__half2*)&b.y;
                v2[6] = *(__half2*)&b.z; v2[7] = *(__half2*)&b.w;
            } else {
                #pragma unroll
                for (int c2 = 0; c2 < 8; c2++) v2[c2] = __half2half2(__float2half(0.f));
            }

            float lg[9];
            #pragma unroll
            for (int q = 0; q < 9; q++) {
                __half2 s = __hmul2(v2[0], v1[q][0]);
                #pragma unroll
                for (int c2 = 1; c2 < 8; c2++) s = __hfma2(v2[c2], v1[q][c2], s);
                float2 f = __half22float2(s);
                lg[q] = (f.x + f.y) * sc;
            }
            float m = lg[0];
            #pragma unroll
            for (int q = 1; q < 9; q++) m = fmaxf(m, lg[q]);
            float s = 0.f;
            float ex[9];
            #pragma unroll
            for (int q = 0; q < 9; q++) { ex[q] = __expf(lg[q] - m); s += ex[q]; }
            float inv = 1.f / s;
            #pragma unroll
            for (int q = 0; q < 9; q++) att[pp*9+q] = ex[q] * inv;
        }
    }

    __half2* catb = g_cat2 + (size_t)(bb*144 + cb2)*HW + p;

    // ---- Phase B: two register passes, v3 via float4 ----
    {
        float oa[5][16];
        #pragma unroll
        for (int pp = 0; pp < 5; pp++)
            #pragma unroll
            for (int c = 0; c < 16; c++) oa[pp][c] = 0.f;
        #pragma unroll 1
        for (int q = 0; q < 9; q++) {
            if (!inb[q]) continue;
            size_t base = (((size_t)br*9 + q)*HBHW + gid + gofs[q])*4;
            float v3[16];
            #pragma unroll
            for (int w = 0; w < 4; w++) {
                float4 f = __ldg(&g_u3v[base + w]);
                v3[4*w] = f.x; v3[4*w+1] = f.y; v3[4*w+2] = f.z; v3[4*w+3] = f.w;
            }
            #pragma unroll
            for (int pp = 0; pp < 5; pp++) {
                float a = att[pp*9+q];
                #pragma unroll
                for (int c = 0; c < 16; c++) oa[pp][c] += a * v3[c];
            }
        }
        #pragma unroll
        for (int pp = 0; pp < 5; pp++)
            #pragma unroll
            for (int c2 = 0; c2 < 8; c2++)
                catb[(size_t)(pp*8 + c2)*HW] = __floats2half2_rn(oa[pp][2*c2], oa[pp][2*c2+1]);
    }
    {
        float oa[4][16];
        #pragma unroll
        for (int pp = 0; pp < 4; pp++)
            #pragma unroll
            for (int c = 0; c < 16; c++) oa[pp][c] = 0.f;
        #pragma unroll 1
        for (int q = 0; q < 9; q++) {
            if (!inb[q]) continue;
            size_t base = (((size_t)br*9 + q)*HBHW + gid + gofs[q])*4;
            float v3[16];
            #pragma unroll
            for (int w = 0; w < 4; w++) {
                float4 f = __ldg(&g_u3v[base + w]);
                v3[4*w] = f.x; v3[4*w+1] = f.y; v3[4*w+2] = f.z; v3[4*w+3] = f.w;
            }
            #pragma unroll
            for (int pp = 0; pp < 4; pp++) {
                float a = att[(pp+5)*9+q];
                #pragma unroll
                for (int c = 0; c < 16; c++) oa[pp][c] += a * v3[c];
            }
        }
        #pragma unroll
        for (int pp = 0; pp < 4; pp++)
            #pragma unroll
            for (int c2 = 0; c2 < 8; c2++)
                catb[(size_t)((pp+5)*8 + c2)*HW] = __floats2half2_rn(oa[pp][2*c2], oa[pp][2*c2+1]);
    }
}

// ---------------- K4: final 1x1 conv via HMMA, 1-term, half2 input -------
__global__ void __launch_bounds__(256)
k_out_mma(const float* __restrict__ bo, float* __restrict__ out)
{
    __shared__ __half Ah[128*36], Bh[128*36];

    int tid  = threadIdx.x;
    int lane = tid & 31;
    int wid  = tid >> 5;
    int wm   = wid >> 1;
    int wn   = wid & 1;

    int pg = blockIdx.x*128;
    int bb = pg / HW;
    int p0 = pg - bb*HW;

    float acc[2][8][4];
    #pragma unroll
    for (int mt = 0; mt < 2; mt++)
        #pragma unroll
        for (int nt = 0; nt < 8; nt++)
            #pragma unroll
            for (int i = 0; i < 4; i++) acc[mt][nt][i] = 0.f;

    int g  = lane >> 2;
    int k0 = 2*(lane & 3);

    for (int i0 = 0; i0 < CCAT; i0 += 32) {
        int cp0 = i0 >> 1;
        __syncthreads();
        for (int idx = tid; idx < 16*128; idx += 256) {
            int c2 = idx >> 7, px = idx & 127;
            __half2 v = g_cat2[(size_t)(bb*144 + cp0 + c2)*HW + p0 + px];
            *(__half2*)&Ah[px*36 + 2*c2] = v;
        }
        {
            int ch = tid & 31;
            int o0 = tid >> 5;
            for (int o = o0; o < COUT; o += 8)
                Bh[o*36 + ch] = g_woh[o*CCAT + i0 + ch];
        }
        __syncthreads();

        #pragma unroll
        for (int ks = 0; ks < 32; ks += 16) {
            uint bh[8][2];
            #pragma unroll
            for (int nt = 0; nt < 8; nt++) {
                int bbase = (wn*64 + nt*8 + g)*36 + ks + k0;
                bh[nt][0] = lduh(&Bh[bbase]); bh[nt][1] = lduh(&Bh[bbase+8]);
            }
            #pragma unroll
            for (int mt = 0; mt < 2; mt++) {
                int ab = (wm*32 + mt*16 + g)*36 + ks + k0;
                uint ah0 = lduh(&Ah[ab]),      ah1 = lduh(&Ah[ab+8*36]);
                uint ah2 = lduh(&Ah[ab+8]),    ah3 = lduh(&Ah[ab+8*36+8]);
                #pragma unroll
                for (int nt = 0; nt < 8; nt++)
                    mma16816(acc[mt][nt], ah0, ah1, ah2, ah3, bh[nt][0], bh[nt][1]);
            }
        }
    }

    float* ob = out + (size_t)bb*COUT*HW;
    #pragma unroll
    for (int mt = 0; mt < 2; mt++) {
        #pragma unroll
        for (int nt = 0; nt < 8; nt++) {
            #pragma unroll
            for (int i = 0; i < 4; i++) {
                int o  = wn*64 + nt*8 + 2*(lane & 3) + (i & 1);
                int px = p0 + wm*32 + mt*16 + (lane >> 2) + ((i >= 2) ? 8 : 0);
                ob[(size_t)o*HW + px] = acc[mt][nt][i] + __ldg(&bo[o]);
            }
        }
    }
}

// ---------------- launcher ----------------
extern "C" void kernel_launch(void* const* d_in, const int* in_sizes, int n_in,
                              void* d_out, int out_size)
{
    const float* cen   = (const float*)d_in[0];
    const float* in_w0 = (const float*)d_in[1];
    const float* in_b0 = (const float*)d_in[2];
    const float* in_w1 = (const float*)d_in[3];
    const float* in_b1 = (const float*)d_in[4];
    const float* w1_0  = (const float*)d_in[5];
    const float* w2_0  = (const float*)d_in[6];
    const float* w3_0  = (const float*)d_in[7];
    const float* w1_1  = (const float*)d_in[8];
    const float* w2_1  = (const float*)d_in[9];
    const float* w3_1  = (const float*)d_in[10];
    const float* scale = (const float*)d_in[11];
    const float* out_w = (const float*)d_in[12];
    const float* out_b = (const float*)d_in[13];
    float* out = (float*)d_out;

    size_t cv_smem = (size_t)(A_PLANE + B_PLANE)*sizeof(__half);         // 42624 B
    size_t ug_smem = (size_t)(128*18 + 432*18 + 144*18)*sizeof(__half)
                   + (size_t)48*130*sizeof(float);                        // 50304 B
    size_t at_smem = (size_t)128*ATTP*sizeof(float);                      // 42496 B
    cudaFuncSetAttribute(k_conv_mma, cudaFuncAttributeMaxDynamicSharedMemorySize,
                         (int)cv_smem);
    cudaFuncSetAttribute(k_ugemm, cudaFuncAttributeMaxDynamicSharedMemorySize,
                         (int)ug_smem);
    cudaFuncSetAttribute(k_attn, cudaFuncAttributeMaxDynamicSharedMemorySize,
                         (int)at_smem);

    int prep_n = 10*16*256 + COUT*CCAT + 2*432*18;
    k_prep<<<(prep_n + 255)/256, 256>>>(in_w1, in_w0, out_w,
                                        w1_0, w2_0, w3_0, w1_1, w2_1, w3_1);
    k_conv_mma<<<576, 256, cv_smem>>>(cen, in_b0, in_b1);
    k_ugemm<<<dim3(HBHW/128, 2), 256, ug_smem>>>();
    k_attn<<<HBHW/128, 128, at_smem>>>(0, 1, scale, 0, 0);
    k_attn<<<HBHW/128, 128, at_smem>>>(1, 5, scale, 1, 72);
    k_out_mma<<<HBHW/128, 256>>>(out_b, out);
}